// round 1
// baseline (speedup 1.0000x reference)
#include <cuda_runtime.h>
#include <cuda_bf16.h>

#define N 8192
#define F 64

// ---------------- scratch (no allocations allowed) ----------------
__device__ float g_ltg[N * F];
__device__ float g_ssrc[N];
__device__ float g_sdst[N];
__device__ float g_P[N];   // exp(s_src)
__device__ float g_p[N];   // exp(0.2 * s_src)
__device__ float g_Qs[N];  // exp(s_dst)
__device__ float g_qs[N];  // exp(0.2 * s_dst)
__device__ int   g_perm[N];            // perm[rank] = original index (ascending s_dst)
__device__ float g_SufQ[(N + 1) * F];  // SufQ[k][f] = sum_{k'>=k} Q*ltg over sorted order
__device__ float g_Preq[(N + 1) * F];  // Preq[k][f] = sum_{k'<k}  q*ltg over sorted order
__device__ float g_SufQs[N + 1];
__device__ float g_Preqs[N + 1];

// ---------------- k1: ltg = graph @ W, attention scalars, exps ----------------
__global__ void k1_gemm(const float* __restrict__ graph,
                        const float* __restrict__ W,
                        const float* __restrict__ a) {
    __shared__ float sW[F * F];
    __shared__ float sa[2 * F];
    int t = threadIdx.x;  // 256 threads
    for (int i = t; i < F * F; i += 256) sW[i] = W[i];
    if (t < 2 * F) sa[t] = a[t];
    __syncthreads();

    int row = blockIdx.x * 256 + t;

    float acc[F];
#pragma unroll
    for (int f = 0; f < F; f++) acc[f] = 0.f;

    const float4* g4 = reinterpret_cast<const float4*>(graph + (size_t)row * F);
#pragma unroll
    for (int k4i = 0; k4i < F / 4; k4i++) {
        float4 g = __ldg(&g4[k4i]);
        float gv[4] = {g.x, g.y, g.z, g.w};
#pragma unroll
        for (int kk = 0; kk < 4; kk++) {
            float gk = gv[kk];
            int k = k4i * 4 + kk;
            const float4* wr = reinterpret_cast<const float4*>(&sW[k * F]);
#pragma unroll
            for (int f4 = 0; f4 < F / 4; f4++) {
                float4 w = wr[f4];
                acc[f4 * 4 + 0] += gk * w.x;
                acc[f4 * 4 + 1] += gk * w.y;
                acc[f4 * 4 + 2] += gk * w.z;
                acc[f4 * 4 + 3] += gk * w.w;
            }
        }
    }

    float ss = 0.f, sd = 0.f;
#pragma unroll
    for (int f = 0; f < F; f++) {
        ss += acc[f] * sa[f];
        sd += acc[f] * sa[F + f];
    }

    float4* lo = reinterpret_cast<float4*>(g_ltg + (size_t)row * F);
#pragma unroll
    for (int f4 = 0; f4 < F / 4; f4++)
        lo[f4] = make_float4(acc[f4 * 4 + 0], acc[f4 * 4 + 1],
                             acc[f4 * 4 + 2], acc[f4 * 4 + 3]);

    g_ssrc[row] = ss;
    g_sdst[row] = sd;
    g_P[row]  = expf(ss);
    g_p[row]  = expf(0.2f * ss);
    g_Qs[row] = expf(sd);
    g_qs[row] = expf(0.2f * sd);
}

// ---------------- k2: rank-by-counting sort (4 keys per warp) ----------------
__global__ void k2_rank() {
    int t = threadIdx.x, lane = t & 31;
    int w = (blockIdx.x * blockDim.x + t) >> 5;  // warp id, 0..N/4-1
    int j0 = w * 4;

    float vj[4];
    int cnt[4] = {0, 0, 0, 0};
#pragma unroll
    for (int r = 0; r < 4; r++) vj[r] = g_sdst[j0 + r];

#pragma unroll 4
    for (int it = 0; it < N / 32; it++) {
        int jp = it * 32 + lane;
        float v = g_sdst[jp];
#pragma unroll
        for (int r = 0; r < 4; r++)
            cnt[r] += (int)((v < vj[r]) || (v == vj[r] && jp < (j0 + r)));
    }

#pragma unroll
    for (int r = 0; r < 4; r++) {
        int c = cnt[r];
#pragma unroll
        for (int o = 16; o; o >>= 1) c += __shfl_down_sync(0xffffffffu, c, o);
        if (lane == 0) g_perm[c] = j0 + r;
    }
}

// ---------------- block-wide inclusive scan (256 threads, double) ----------------
__device__ __forceinline__ double bscan256(double v, double& total) {
    __shared__ double shw[8];
    __shared__ double shtot;
    __syncthreads();  // protect shared reuse across successive calls
    int t = threadIdx.x, lane = t & 31, wp = t >> 5;
    double x = v;
#pragma unroll
    for (int o = 1; o < 32; o <<= 1) {
        double n = __shfl_up_sync(0xffffffffu, x, o);
        if (lane >= o) x += n;
    }
    if (lane == 31) shw[wp] = x;
    __syncthreads();
    if (t == 0) {
        double run = 0.0;
#pragma unroll
        for (int i2 = 0; i2 < 8; i2++) {
            double tmp = shw[i2];
            shw[i2] = run;   // exclusive warp offsets
            run += tmp;
        }
        shtot = run;
    }
    __syncthreads();
    total = shtot;
    return x + shw[wp];  // inclusive
}

// ---------------- k3: prefix(q*ltg) and suffix(Q*ltg) over sorted order -------
// blocks 0..63 -> feature column f; block 64 -> scalar sums
__global__ void k3_scan() {
    int f = blockIdx.x;
    int t = threadIdx.x;  // 256

    if (f < F) {
        float vq[32], vQ[32];
        double myQ = 0.0;
#pragma unroll
        for (int r2 = 0; r2 < 32; r2++) {
            int k = r2 * 256 + t;
            int j = g_perm[k];
            float l = g_ltg[(size_t)j * F + f];
            vq[r2] = g_qs[j] * l;
            vQ[r2] = g_Qs[j] * l;
            myQ += (double)vQ[r2];
        }
        double totQ;
        bscan256(myQ, totQ);

        double cq = 0.0, cQ = 0.0;
#pragma unroll
        for (int r2 = 0; r2 < 32; r2++) {
            int k = r2 * 256 + t;
            double tq, tQ2;
            double iq = bscan256((double)vq[r2], tq);
            double iQ = bscan256((double)vQ[r2], tQ2);
            g_Preq[(size_t)k * F + f] = (float)(cq + iq - (double)vq[r2]);
            g_SufQ[(size_t)k * F + f] = (float)(totQ - (cQ + iQ - (double)vQ[r2]));
            cq += tq;
            cQ += tQ2;
        }
        if (t == 0) {
            g_Preq[(size_t)N * F + f] = (float)cq;
            g_SufQ[(size_t)N * F + f] = 0.f;
        }
    } else {
        float vq[32], vQ[32];
        double myQ = 0.0;
#pragma unroll
        for (int r2 = 0; r2 < 32; r2++) {
            int k = r2 * 256 + t;
            int j = g_perm[k];
            vq[r2] = g_qs[j];
            vQ[r2] = g_Qs[j];
            myQ += (double)vQ[r2];
        }
        double totQ;
        bscan256(myQ, totQ);

        double cq = 0.0, cQ = 0.0;
#pragma unroll
        for (int r2 = 0; r2 < 32; r2++) {
            int k = r2 * 256 + t;
            double tq, tQ2;
            double iq = bscan256((double)vq[r2], tq);
            double iQ = bscan256((double)vQ[r2], tQ2);
            g_Preqs[k] = (float)(cq + iq - (double)vq[r2]);
            g_SufQs[k] = (float)(totQ - (cQ + iQ - (double)vQ[r2]));
            cq += tq;
            cQ += tQ2;
        }
        if (t == 0) {
            g_Preqs[N] = (float)cq;
            g_SufQs[N] = 0.f;
        }
    }
}

// ---------------- k4: threshold count + combine (4 rows per warp) -------------
__global__ void k4_out(float* __restrict__ out) {
    int t = threadIdx.x, lane = t & 31;
    int w = (blockIdx.x * blockDim.x + t) >> 5;  // warp id 0..N/4-1
    int i0 = w * 4;

    float ti[4];
    int cnt[4] = {0, 0, 0, 0};
#pragma unroll
    for (int r = 0; r < 4; r++) ti[r] = -g_ssrc[i0 + r];

#pragma unroll 4
    for (int it = 0; it < N / 32; it++) {
        float v = g_sdst[it * 32 + lane];
#pragma unroll
        for (int r = 0; r < 4; r++) cnt[r] += (int)(v < ti[r]);
    }

#pragma unroll
    for (int r = 0; r < 4; r++) {
        int c = cnt[r];
#pragma unroll
        for (int o = 16; o; o >>= 1) c += __shfl_down_sync(0xffffffffu, c, o);
        c = __shfl_sync(0xffffffffu, c, 0);

        int i = i0 + r;
        float P = g_P[i], p = g_p[i];
        float Z = P * g_SufQs[c] + p * g_Preqs[c];
        float invZ = 1.0f / Z;
#pragma unroll
        for (int h = 0; h < 2; h++) {
            int f = lane + 32 * h;
            out[(size_t)i * F + f] =
                (P * g_SufQ[(size_t)c * F + f] + p * g_Preq[(size_t)c * F + f]) * invZ;
        }
    }
}

// ---------------- launch ----------------
extern "C" void kernel_launch(void* const* d_in, const int* in_sizes, int n_in,
                              void* d_out, int out_size) {
    const float* graph = (const float*)d_in[0];
    const float* W     = (const float*)d_in[1];
    const float* a     = (const float*)d_in[2];
    float* out = (float*)d_out;

    k1_gemm<<<N / 256, 256>>>(graph, W, a);
    k2_rank<<<N / 4 / 8, 256>>>();   // N/4 warps, 8 warps/block
    k3_scan<<<F + 1, 256>>>();
    k4_out<<<N / 4 / 8, 256>>>(out);
}

// round 3
// speedup vs baseline: 1.3636x; 1.3636x over previous
#include <cuda_runtime.h>
#include <cuda_bf16.h>

#define N 8192
#define F 64
#define KSPLIT 4
#define JCHUNK (N / KSPLIT)  // 2048

// ---------------- scratch (no allocations allowed) ----------------
__device__ float g_ltg[N * F];
__device__ float g_ssrc[N];
__device__ float g_sdst[N];
__device__ float g_P[N];   // exp(s_src)
__device__ float g_p[N];   // exp(0.2 * s_src)
__device__ float g_Qs[N];  // exp(s_dst)
__device__ float g_qs[N];  // exp(0.2 * s_dst)
__device__ unsigned long long g_key[N];  // (sortable(sdst) << 32) | idx — unique keys
__device__ int   g_pcnt[KSPLIT][N];      // partial rank counts
__device__ int   g_perm[N];              // perm[rank] = original index (ascending sdst)
__device__ float g_sorted[N];            // sdst values in ascending order
__device__ float g_SufQ[(N + 1) * F];    // SufQ[k][f] = sum_{k'>=k} Q*ltg over sorted order
__device__ float g_Preq[(N + 1) * F];    // Preq[k][f] = sum_{k'<k}  q*ltg over sorted order
__device__ float g_SufQs[N + 1];
__device__ float g_Preqs[N + 1];

__device__ __forceinline__ unsigned int f2sort(float f) {
    unsigned int u = __float_as_uint(f);
    return (u & 0x80000000u) ? ~u : (u | 0x80000000u);
}

// ---------------- k1: ltg = graph @ W, attention scalars, exps, keys ----------
__global__ void k1_gemm(const float* __restrict__ graph,
                        const float* __restrict__ W,
                        const float* __restrict__ a) {
    __shared__ float sW[F * F];
    __shared__ float sa[2 * F];
    int t = threadIdx.x;  // 128 threads
    for (int i = t; i < F * F; i += 128) sW[i] = W[i];
    if (t < 2 * F) sa[t] = a[t];
    __syncthreads();

    int row = blockIdx.x * 128 + t;

    float acc[F];
#pragma unroll
    for (int f = 0; f < F; f++) acc[f] = 0.f;

    const float4* g4 = reinterpret_cast<const float4*>(graph + (size_t)row * F);
#pragma unroll
    for (int k4i = 0; k4i < F / 4; k4i++) {
        float4 g = __ldg(&g4[k4i]);
        float gv[4] = {g.x, g.y, g.z, g.w};
#pragma unroll
        for (int kk = 0; kk < 4; kk++) {
            float gk = gv[kk];
            int k = k4i * 4 + kk;
            const float4* wr = reinterpret_cast<const float4*>(&sW[k * F]);
#pragma unroll
            for (int f4 = 0; f4 < F / 4; f4++) {
                float4 w = wr[f4];
                acc[f4 * 4 + 0] += gk * w.x;
                acc[f4 * 4 + 1] += gk * w.y;
                acc[f4 * 4 + 2] += gk * w.z;
                acc[f4 * 4 + 3] += gk * w.w;
            }
        }
    }

    float ss = 0.f, sd = 0.f;
#pragma unroll
    for (int f = 0; f < F; f++) {
        ss += acc[f] * sa[f];
        sd += acc[f] * sa[F + f];
    }

    float4* lo = reinterpret_cast<float4*>(g_ltg + (size_t)row * F);
#pragma unroll
    for (int f4 = 0; f4 < F / 4; f4++)
        lo[f4] = make_float4(acc[f4 * 4 + 0], acc[f4 * 4 + 1],
                             acc[f4 * 4 + 2], acc[f4 * 4 + 3]);

    g_ssrc[row] = ss;
    g_sdst[row] = sd;
    g_P[row]  = expf(ss);
    g_p[row]  = expf(0.2f * ss);
    g_Qs[row] = expf(sd);
    g_qs[row] = expf(0.2f * sd);
    g_key[row] = ((unsigned long long)f2sort(sd) << 32) | (unsigned int)row;
}

// ---------------- k2: partial rank counts via shared-staged compares ----------
// 128 blocks: blockIdx = keygroup (0..31) + 32*split (0..3).
// Each thread owns one key (register); block stages its j-chunk in shared.
__global__ void k2_count() {
    __shared__ unsigned long long sk[JCHUNK];
    int t = threadIdx.x;  // 256
    int g = blockIdx.x & 31;
    int s = blockIdx.x >> 5;

    const ulonglong2* src = reinterpret_cast<const ulonglong2*>(g_key + s * JCHUNK);
    ulonglong2* dst = reinterpret_cast<ulonglong2*>(sk);
    for (int i = t; i < JCHUNK / 2; i += 256) dst[i] = src[i];

    unsigned long long mykey = g_key[g * 256 + t];
    __syncthreads();

    const ulonglong2* skv = reinterpret_cast<const ulonglong2*>(sk);
    int cnt = 0;
#pragma unroll 8
    for (int j = 0; j < JCHUNK / 2; j++) {
        ulonglong2 v = skv[j];
        cnt += (int)(v.x < mykey) + (int)(v.y < mykey);
    }
    g_pcnt[s][g * 256 + t] = cnt;
}

// ---------------- k2b: combine partials, scatter perm + sorted values --------
__global__ void k2b_scatter() {
    int i = blockIdx.x * 256 + threadIdx.x;
    int c = g_pcnt[0][i] + g_pcnt[1][i] + g_pcnt[2][i] + g_pcnt[3][i];
    g_perm[c] = i;
    g_sorted[c] = g_sdst[i];
}

// ---------------- paired block-wide inclusive scan (256 threads, double2) ----
__device__ __forceinline__ double2 bscan2(double2 v, double2& total) {
    __shared__ double sx[8], sy[8];
    __shared__ double stx, sty;
    __syncthreads();  // protect shared reuse across successive calls
    int t = threadIdx.x, lane = t & 31, wp = t >> 5;
    double x = v.x, y = v.y;
#pragma unroll
    for (int o = 1; o < 32; o <<= 1) {
        double nx = __shfl_up_sync(0xffffffffu, x, o);
        double ny = __shfl_up_sync(0xffffffffu, y, o);
        if (lane >= o) { x += nx; y += ny; }
    }
    if (lane == 31) { sx[wp] = x; sy[wp] = y; }
    __syncthreads();
    if (t == 0) {
        double rx = 0.0, ry = 0.0;
#pragma unroll
        for (int i2 = 0; i2 < 8; i2++) {
            double tx = sx[i2], ty = sy[i2];
            sx[i2] = rx; sy[i2] = ry;  // exclusive warp offsets
            rx += tx; ry += ty;
        }
        stx = rx; sty = ry;
    }
    __syncthreads();
    total = make_double2(stx, sty);
    return make_double2(x + sx[wp], y + sy[wp]);  // inclusive
}

// ---------------- k3: prefix(q*ltg) and suffix(Q*ltg) over sorted order ------
// blocks 0..63 -> feature column f; block 64 -> scalar sums
__global__ void k3_scan() {
    int f = blockIdx.x;
    int t = threadIdx.x;  // 256

    if (f < F) {
        float vq[32], vQ[32];
        double2 my = make_double2(0.0, 0.0);
#pragma unroll
        for (int r2 = 0; r2 < 32; r2++) {
            int k = r2 * 256 + t;
            int j = g_perm[k];
            float l = g_ltg[(size_t)j * F + f];
            vq[r2] = g_qs[j] * l;
            vQ[r2] = g_Qs[j] * l;
            my.y += (double)vQ[r2];
        }
        double2 tot;
        bscan2(my, tot);
        double totQ = tot.y;

        double cq = 0.0, cQ = 0.0;
#pragma unroll
        for (int r2 = 0; r2 < 32; r2++) {
            int k = r2 * 256 + t;
            double2 tt;
            double2 inc = bscan2(make_double2((double)vq[r2], (double)vQ[r2]), tt);
            g_Preq[(size_t)k * F + f] = (float)(cq + inc.x - (double)vq[r2]);
            g_SufQ[(size_t)k * F + f] = (float)(totQ - (cQ + inc.y - (double)vQ[r2]));
            cq += tt.x;
            cQ += tt.y;
        }
        if (t == 0) {
            g_Preq[(size_t)N * F + f] = (float)cq;
            g_SufQ[(size_t)N * F + f] = 0.f;
        }
    } else {
        float vq[32], vQ[32];
        double2 my = make_double2(0.0, 0.0);
#pragma unroll
        for (int r2 = 0; r2 < 32; r2++) {
            int k = r2 * 256 + t;
            int j = g_perm[k];
            vq[r2] = g_qs[j];
            vQ[r2] = g_Qs[j];
            my.y += (double)vQ[r2];
        }
        double2 tot;
        bscan2(my, tot);
        double totQ = tot.y;

        double cq = 0.0, cQ = 0.0;
#pragma unroll
        for (int r2 = 0; r2 < 32; r2++) {
            int k = r2 * 256 + t;
            double2 tt;
            double2 inc = bscan2(make_double2((double)vq[r2], (double)vQ[r2]), tt);
            g_Preqs[k] = (float)(cq + inc.x - (double)vq[r2]);
            g_SufQs[k] = (float)(totQ - (cQ + inc.y - (double)vQ[r2]));
            cq += tt.x;
            cQ += tt.y;
        }
        if (t == 0) {
            g_Preqs[N] = (float)cq;
            g_SufQs[N] = 0.f;
        }
    }
}

// ---------------- k4: binary-search rank + combine (warp per row) ------------
__global__ void k4_out(float* __restrict__ out) {
    int t = threadIdx.x, lane = t & 31;
    int row = blockIdx.x * 8 + (t >> 5);  // 8 warps/block, one row per warp

    float target = -g_ssrc[row];

    // lower_bound: c = #{j : sdst[j] < target}  (all lanes redundantly, broadcast loads)
    int lo = 0, hi = N;
#pragma unroll
    for (int step = 0; step < 13; step++) {
        int mid = (lo + hi) >> 1;
        if (g_sorted[mid] < target) lo = mid + 1; else hi = mid;
    }
    int c = lo;

    float P = g_P[row], p = g_p[row];
    float Z = P * g_SufQs[c] + p * g_Preqs[c];
    float invZ = 1.0f / Z;
#pragma unroll
    for (int h = 0; h < 2; h++) {
        int f = lane + 32 * h;
        out[(size_t)row * F + f] =
            (P * g_SufQ[(size_t)c * F + f] + p * g_Preq[(size_t)c * F + f]) * invZ;
    }
}

// ---------------- launch ----------------
extern "C" void kernel_launch(void* const* d_in, const int* in_sizes, int n_in,
                              void* d_out, int out_size) {
    const float* graph = (const float*)d_in[0];
    const float* W     = (const float*)d_in[1];
    const float* a     = (const float*)d_in[2];
    float* out = (float*)d_out;

    k1_gemm<<<N / 128, 128>>>(graph, W, a);
    k2_count<<<32 * KSPLIT, 256>>>();
    k2b_scatter<<<N / 256, 256>>>();
    k3_scan<<<F + 1, 256>>>();
    k4_out<<<N / 8, 256>>>(out);
}

// round 4
// speedup vs baseline: 1.4516x; 1.0645x over previous
#include <cuda_runtime.h>
#include <cuda_bf16.h>

#define N 8192
#define F 64
#define JSPLIT 64
#define JC2 (N / JSPLIT)   // 128 j-values staged per k2 block
#define CH 32              // scan chunks
#define CHSZ (N / CH)      // 256

// ---------------- scratch (no allocations allowed) ----------------
__device__ float g_ltg[N * F];
__device__ float g_ssrc[N];
__device__ float g_sdst[N];
__device__ float g_P[N];   // exp(s_src)
__device__ float g_p[N];   // exp(0.2 * s_src)
__device__ float g_Qs[N];  // exp(s_dst)
__device__ float g_qs[N];  // exp(0.2 * s_dst)
__device__ unsigned long long g_key[N];  // (sortable(sdst) << 32) | idx — unique
__device__ int   g_pcnt[JSPLIT][N];      // partial rank counts
__device__ int   g_perm[N];              // perm[rank] = original index
__device__ float g_sorted[N];            // sdst ascending
__device__ double g_ctq[F + 1][CH];      // chunk totals (q side)
__device__ double g_ctQ[F + 1][CH];      // chunk totals (Q side)
__device__ float g_SufQ[(N + 1) * F];
__device__ float g_Preq[(N + 1) * F];
__device__ float g_SufQs[N + 1];
__device__ float g_Preqs[N + 1];

__device__ __forceinline__ unsigned int f2sort(float f) {
    unsigned int u = __float_as_uint(f);
    return (u & 0x80000000u) ? ~u : (u | 0x80000000u);
}

// ---------------- k1: ltg = graph @ W + scalars; 4 threads per row ------------
__global__ void k1_gemm(const float* __restrict__ graph,
                        const float* __restrict__ W,
                        const float* __restrict__ a) {
    __shared__ float sW[F * F];
    __shared__ float sa[2 * F];
    int t = threadIdx.x;  // 256
    for (int i = t; i < F * F; i += 256) sW[i] = W[i];
    if (t < 2 * F) sa[t] = a[t];
    __syncthreads();

    int row = blockIdx.x * 64 + (t >> 2);
    int fs = (t & 3) * 16;  // this thread's 16-feature sub-block

    float acc[16];
#pragma unroll
    for (int f = 0; f < 16; f++) acc[f] = 0.f;

    const float4* g4 = reinterpret_cast<const float4*>(graph + (size_t)row * F);
#pragma unroll
    for (int k4i = 0; k4i < F / 4; k4i++) {
        float4 g = __ldg(&g4[k4i]);
        float gv[4] = {g.x, g.y, g.z, g.w};
#pragma unroll
        for (int kk = 0; kk < 4; kk++) {
            float gk = gv[kk];
            const float4* wr = reinterpret_cast<const float4*>(&sW[(k4i * 4 + kk) * F + fs]);
#pragma unroll
            for (int f4 = 0; f4 < 4; f4++) {
                float4 w = wr[f4];
                acc[f4 * 4 + 0] += gk * w.x;
                acc[f4 * 4 + 1] += gk * w.y;
                acc[f4 * 4 + 2] += gk * w.z;
                acc[f4 * 4 + 3] += gk * w.w;
            }
        }
    }

    float ss = 0.f, sd = 0.f;
#pragma unroll
    for (int f = 0; f < 16; f++) {
        ss += acc[f] * sa[fs + f];
        sd += acc[f] * sa[F + fs + f];
    }
    ss += __shfl_xor_sync(0xffffffffu, ss, 1);
    ss += __shfl_xor_sync(0xffffffffu, ss, 2);
    sd += __shfl_xor_sync(0xffffffffu, sd, 1);
    sd += __shfl_xor_sync(0xffffffffu, sd, 2);

    float4* lo = reinterpret_cast<float4*>(g_ltg + (size_t)row * F + fs);
#pragma unroll
    for (int f4 = 0; f4 < 4; f4++)
        lo[f4] = make_float4(acc[f4 * 4 + 0], acc[f4 * 4 + 1],
                             acc[f4 * 4 + 2], acc[f4 * 4 + 3]);

    if ((t & 3) == 0) {
        g_ssrc[row] = ss;
        g_sdst[row] = sd;
        g_P[row]  = expf(ss);
        g_p[row]  = expf(0.2f * ss);
        g_Qs[row] = expf(sd);
        g_qs[row] = expf(0.2f * sd);
        g_key[row] = ((unsigned long long)f2sort(sd) << 32) | (unsigned int)row;
    }
}

// ---------------- k2: rank counts, 8 register keys per thread ----------------
// 256 blocks: g = keygroup (0..3, 2048 keys), s = j-split (0..63, 128 values)
__global__ void k2_count() {
    __shared__ unsigned long long sk[JC2];
    int t = threadIdx.x;  // 256
    int g = blockIdx.x & 3;
    int s = blockIdx.x >> 2;

    if (t < JC2) sk[t] = g_key[s * JC2 + t];

    unsigned long long key[8];
    int base = g * 2048 + t;
#pragma unroll
    for (int r = 0; r < 8; r++) key[r] = g_key[base + 256 * r];
    __syncthreads();

    int cnt[8];
#pragma unroll
    for (int r = 0; r < 8; r++) cnt[r] = 0;

    const ulonglong2* skv = reinterpret_cast<const ulonglong2*>(sk);
#pragma unroll 8
    for (int jj = 0; jj < JC2 / 2; jj++) {
        ulonglong2 v = skv[jj];
#pragma unroll
        for (int r = 0; r < 8; r++)
            cnt[r] += (int)(v.x < key[r]) + (int)(v.y < key[r]);
    }
#pragma unroll
    for (int r = 0; r < 8; r++) g_pcnt[s][base + 256 * r] = cnt[r];
}

// ---------------- k2b: combine partials, scatter perm + sorted values --------
__global__ void k2b_scatter() {
    int i = blockIdx.x * 256 + threadIdx.x;
    int c = 0;
#pragma unroll
    for (int s = 0; s < JSPLIT; s++) c += g_pcnt[s][i];
    g_perm[c] = i;
    g_sorted[c] = g_sdst[i];
}

// ---------------- k3a: per-chunk double totals (block reduce) ----------------
__global__ void k3a_tot() {
    int chunk = blockIdx.x, f = blockIdx.y;
    int t = threadIdx.x, lane = t & 31, wp = t >> 5;  // 256 threads

    int k = chunk * CHSZ + t;
    int j = g_perm[k];
    double vq, vQ;
    if (f < F) {
        float l = g_ltg[(size_t)j * F + f];
        vq = (double)(g_qs[j] * l);
        vQ = (double)(g_Qs[j] * l);
    } else {
        vq = (double)g_qs[j];
        vQ = (double)g_Qs[j];
    }
#pragma unroll
    for (int o = 16; o; o >>= 1) {
        vq += __shfl_down_sync(0xffffffffu, vq, o);
        vQ += __shfl_down_sync(0xffffffffu, vQ, o);
    }
    __shared__ double rx[8], ry[8];
    if (lane == 0) { rx[wp] = vq; ry[wp] = vQ; }
    __syncthreads();
    if (t == 0) {
        double sq = 0.0, sQ = 0.0;
#pragma unroll
        for (int i2 = 0; i2 < 8; i2++) { sq += rx[i2]; sQ += ry[i2]; }
        g_ctq[f][chunk] = sq;
        g_ctQ[f][chunk] = sQ;
    }
}

// ---------------- paired block-wide inclusive scan (256 threads, double2) ----
__device__ __forceinline__ double2 bscan2(double2 v, double2& total) {
    __shared__ double sx[8], sy[8];
    __shared__ double stx, sty;
    __syncthreads();
    int t = threadIdx.x, lane = t & 31, wp = t >> 5;
    double x = v.x, y = v.y;
#pragma unroll
    for (int o = 1; o < 32; o <<= 1) {
        double nx = __shfl_up_sync(0xffffffffu, x, o);
        double ny = __shfl_up_sync(0xffffffffu, y, o);
        if (lane >= o) { x += nx; y += ny; }
    }
    if (lane == 31) { sx[wp] = x; sy[wp] = y; }
    __syncthreads();
    if (t == 0) {
        double rxx = 0.0, ryy = 0.0;
#pragma unroll
        for (int i2 = 0; i2 < 8; i2++) {
            double tx = sx[i2], ty = sy[i2];
            sx[i2] = rxx; sy[i2] = ryy;
            rxx += tx; ryy += ty;
        }
        stx = rxx; sty = ryy;
    }
    __syncthreads();
    total = make_double2(stx, sty);
    return make_double2(x + sx[wp], y + sy[wp]);
}

// ---------------- k3c: chunk offsets + one block scan + final write ----------
__global__ void k3c_scan() {
    int chunk = blockIdx.x, f = blockIdx.y;
    int t = threadIdx.x;  // 256

    __shared__ double s_offq, s_offQ, s_totq, s_totQ;
    if (t < 32) {
        double cq = g_ctq[f][t], cQ = g_ctQ[f][t];
        double iq = cq, iQ = cQ;
#pragma unroll
        for (int o = 1; o < 32; o <<= 1) {
            double nq = __shfl_up_sync(0xffffffffu, iq, o);
            double nQ = __shfl_up_sync(0xffffffffu, iQ, o);
            if (t >= o) { iq += nq; iQ += nQ; }
        }
        if (t == 31) { s_totq = iq; s_totQ = iQ; }
        if (t == chunk) { s_offq = iq - cq; s_offQ = iQ - cQ; }
    }

    int k = chunk * CHSZ + t;
    int j = g_perm[k];
    float vq, vQ;
    if (f < F) {
        float l = g_ltg[(size_t)j * F + f];
        vq = g_qs[j] * l;
        vQ = g_Qs[j] * l;
    } else {
        vq = g_qs[j];
        vQ = g_Qs[j];
    }

    double2 tt;
    double2 inc = bscan2(make_double2((double)vq, (double)vQ), tt);
    // bscan2's internal syncthreads make s_off/s_tot visible here

    if (f < F) {
        g_Preq[(size_t)k * F + f] = (float)(s_offq + inc.x - (double)vq);
        g_SufQ[(size_t)k * F + f] = (float)(s_totQ - (s_offQ + inc.y - (double)vQ));
        if (k == 0) {
            g_Preq[(size_t)N * F + f] = (float)s_totq;
            g_SufQ[(size_t)N * F + f] = 0.f;
        }
    } else {
        g_Preqs[k] = (float)(s_offq + inc.x - (double)vq);
        g_SufQs[k] = (float)(s_totQ - (s_offQ + inc.y - (double)vQ));
        if (k == 0) {
            g_Preqs[N] = (float)s_totq;
            g_SufQs[N] = 0.f;
        }
    }
}

// ---------------- k4: binary-search rank + coalesced combine -----------------
__global__ void k4_out(float* __restrict__ out) {
    __shared__ int   sc[64];
    __shared__ float sP[64], sp[64], sZ[64];
    int t = threadIdx.x;  // 256
    int base = blockIdx.x * 64;

    if (t < 64) {
        int row = base + t;
        float target = -g_ssrc[row];
        int lo = 0, hi = N;
#pragma unroll
        for (int step = 0; step < 13; step++) {
            int mid = (lo + hi) >> 1;
            if (g_sorted[mid] < target) lo = mid + 1; else hi = mid;
        }
        int c = lo;
        float P = g_P[row], p = g_p[row];
        float Z = P * g_SufQs[c] + p * g_Preqs[c];
        sc[t] = c; sP[t] = P; sp[t] = p; sZ[t] = 1.0f / Z;
    }
    __syncthreads();

    int f = t & 63;
    int rsub = t >> 6;  // 0..3
#pragma unroll
    for (int it = 0; it < 16; it++) {
        int rl = it * 4 + rsub;
        int c = sc[rl];
        float val = (sP[rl] * g_SufQ[(size_t)c * F + f] +
                     sp[rl] * g_Preq[(size_t)c * F + f]) * sZ[rl];
        out[(size_t)(base + rl) * F + f] = val;
    }
}

// ---------------- launch ----------------
extern "C" void kernel_launch(void* const* d_in, const int* in_sizes, int n_in,
                              void* d_out, int out_size) {
    const float* graph = (const float*)d_in[0];
    const float* W     = (const float*)d_in[1];
    const float* a     = (const float*)d_in[2];
    float* out = (float*)d_out;

    k1_gemm<<<N / 64, 256>>>(graph, W, a);
    k2_count<<<4 * JSPLIT, 256>>>();
    k2b_scatter<<<N / 256, 256>>>();
    k3a_tot<<<dim3(CH, F + 1), 256>>>();
    k3c_scan<<<dim3(CH, F + 1), 256>>>();
    k4_out<<<N / 64, 256>>>(out);
}